// round 4
// baseline (speedup 1.0000x reference)
#include <cuda_runtime.h>
#include <math.h>

#define Bn 32
#define Nn 262144
#define Gn 256
#define SEGSZ 2048              // elements per warp-segment
#define SEGPB (Nn / SEGSZ)      // 128 segments per batch
#define NSEG (Bn * SEGPB)       // 4096 segments
#define NWARP 8                 // warps per block (hist/scatter)
#define CHUNK 16384
#define NBLK ((Bn * Nn) / CHUNK)   // 512

// ---------------- scratch (device globals; no allocation) ----------------
__device__ unsigned g_cnt[NSEG][Gn];   // per-segment counts -> within-batch exclusive prefix
__device__ unsigned g_base[Bn][Gn];    // group base offset within batch
__device__ unsigned g_tot[Bn][Gn];     // group totals
__device__ float    g_sorted[Bn * Nn]; // stable-partitioned pr (n-order within group)
__device__ float4   g_P[Bn * Gn];      // per-group (mn', rng, df, f0')

__device__ __forceinline__ bool bit_isnan(float f) {
    return (__float_as_uint(f) << 1) > 0xFF000000u;
}
__device__ __forceinline__ bool bit_iszero(float f) {
    return (__float_as_uint(f) << 1) == 0u;
}
__device__ __forceinline__ bool bit_nonfinite(float f) {
    return (__float_as_uint(f) << 1) >= 0xFF000000u;
}

// ---------------- kernel 1: per-segment histogram (warp-private) ---------
__global__ __launch_bounds__(256) void k_hist(const int* __restrict__ vr) {
    __shared__ unsigned s_h[NWARP][Gn];
    int t = threadIdx.x, w = t >> 5, l = t & 31;
    unsigned lt = (1u << l) - 1u;

#pragma unroll
    for (int i = l; i < Gn; i += 32) s_h[w][i] = 0u;
    __syncwarp();

    long seg = (long)blockIdx.x * NWARP + w;
    const int* __restrict__ src = vr + seg * SEGSZ;

#pragma unroll 4
    for (int r = 0; r < SEGSZ / 32; ++r) {
        int g = src[r * 32 + l];
        unsigned m = __match_any_sync(0xFFFFFFFFu, g);
        if ((m & lt) == 0u) s_h[w][g] += __popc(m);   // unique leader per group/round
    }
    __syncwarp();

#pragma unroll
    for (int i = l; i < Gn; i += 32) g_cnt[seg][i] = s_h[w][i];
}

// ---------------- kernel 2: scans (per-batch) ----------------------------
__global__ __launch_bounds__(Gn) void k_scan() {
    int b = blockIdx.x;
    int g = threadIdx.x;

    unsigned run = 0;
#pragma unroll 4
    for (int s = 0; s < SEGPB; ++s) {
        int idx = b * SEGPB + s;
        unsigned c = g_cnt[idx][g];
        g_cnt[idx][g] = run;          // exclusive prefix within batch, per group
        run += c;
    }
    g_tot[b][g] = run;

    __shared__ unsigned sh[Gn];
    sh[g] = run;
    __syncthreads();
    for (int d = 1; d < Gn; d <<= 1) {
        unsigned x = (g >= d) ? sh[g - d] : 0u;
        __syncthreads();
        sh[g] += x;
        __syncthreads();
    }
    g_base[b][g] = sh[g] - run;       // exclusive scan over groups
}

// ---------------- kernel 3: stable scatter (warp-segment, barrier-free) --
__global__ __launch_bounds__(256) void k_scatter(const float* __restrict__ pr,
                                                 const int* __restrict__ vr) {
    __shared__ unsigned s_run[NWARP][Gn];
    int t = threadIdx.x, w = t >> 5, l = t & 31;
    unsigned lt = (1u << l) - 1u;

    long seg = (long)blockIdx.x * NWARP + w;
    int b = (int)(seg >> 7);          // seg / SEGPB

#pragma unroll
    for (int i = l; i < Gn; i += 32)
        s_run[w][i] = g_base[b][i] + g_cnt[seg][i];
    __syncwarp();

    const int*   __restrict__ vs = vr + seg * SEGSZ;
    const float* __restrict__ ps = pr + seg * SEGSZ;
    float* __restrict__ dst = g_sorted + (long)b * Nn;

#pragma unroll 4
    for (int r = 0; r < SEGSZ / 32; ++r) {
        int   g = vs[r * 32 + l];
        float p = ps[r * 32 + l];
        unsigned m = __match_any_sync(0xFFFFFFFFu, g);
        unsigned lr = __popc(m & lt);
        unsigned cur = s_run[w][g];          // all lanes read (program-ordered vs write)
        dst[cur + lr] = p;
        if (lr == 0u) s_run[w][g] = cur + __popc(m);
    }
}

// ---------------- kernel 4: sequential fold + min/max + sort + params ----
__global__ __launch_bounds__(Gn) void k_params(const float* __restrict__ inp_means,
                                               const float* __restrict__ W) {
    __shared__ float skey[Gn];
    __shared__ int   sid[Gn];
    __shared__ float f0u[Gn];
    __shared__ float f1u[Gn];

    int b = blockIdx.x;
    int g = threadIdx.x;
    int o = b * Gn + g;

    // exact sequential fp32 fold over the group's elements in n-order
    unsigned cnt  = g_tot[b][g];
    unsigned base = g_base[b][g];
    const float* __restrict__ src = g_sorted + (long)b * Nn + base;
    float acc = 0.0f;
    float mn =  __int_as_float(0x7F800000);   // +inf
    float mx = -__int_as_float(0x7F800000);   // -inf
    unsigned i = 0;
#pragma unroll 4
    for (; i + 4 <= cnt; i += 4) {
        float a0 = src[i], a1 = src[i + 1], a2 = src[i + 2], a3 = src[i + 3];
        acc = __fadd_rn(acc, a0);
        acc = __fadd_rn(acc, a1);
        acc = __fadd_rn(acc, a2);
        acc = __fadd_rn(acc, a3);
        mn = fminf(mn, fminf(fminf(a0, a1), fminf(a2, a3)));
        mx = fmaxf(mx, fmaxf(fmaxf(a0, a1), fmaxf(a2, a3)));
    }
    for (; i < cnt; ++i) {
        float a0 = src[i];
        acc = __fadd_rn(acc, a0);
        mn = fminf(mn, a0);
        mx = fmaxf(mx, a0);
    }

    bool any = (cnt > 0u);
    float vsum = any ? acc : 0.0f;

    float W0 = W[0], W1 = W[1];
    float vmean = __fdiv_rn(__fadd_rn(__fmul_rn(inp_means[o], W0),
                                      __fmul_rn(vsum, W1)),
                            __fadd_rn(W0, W1));

    skey[g] = vmean;
    sid[g]  = g;
    __syncthreads();

    // bitonic sort on (value, id) == jax stable argsort
    for (int k = 2; k <= Gn; k <<= 1) {
        for (int j = k >> 1; j > 0; j >>= 1) {
            int ixj = g ^ j;
            if (ixj > g) {
                float a = skey[g], c = skey[ixj];
                int ia = sid[g], ic = sid[ixj];
                bool up = ((g & k) == 0);
                bool gt = (a > c) || (a == c && ia > ic);
                if (gt == up) {
                    skey[g] = c; skey[ixj] = a;
                    sid[g] = ic; sid[ixj] = ia;
                }
            }
            __syncthreads();
        }
    }

    float vsr   = skey[g];
    float vprev = (g == 0)      ? vsr : skey[g - 1];
    float vnext = (g == Gn - 1) ? __fmul_rn(vsr, 2.0f) : skey[g + 1];
    float f0 = __fdiv_rn(__fadd_rn(vprev, vsr), 1.999f);
    float f1 = __fdiv_rn(__fadd_rn(vsr, vnext), 2.001f);
    f0u[sid[g]] = f0;
    f1u[sid[g]] = f1;
    __syncthreads();

    bool ns = (mn == mx);   // empty group: inf == -inf -> false (matches ref)

    float mn2, mx2, f02, f12;
    if (!any) { mn2 = 0.0f; mx2 = 1.0f; f02 = 0.0f; f12 = 0.0f; }
    else {
        mn2 = ns ? 0.0f : mn;
        mx2 = ns ? 1.0f : mx;
        f02 = ns ? 0.0f : f0u[g];
        f12 = ns ? 1.0f : f1u[g];
    }
    float rng = __fsub_rn(mx2, mn2);
    float df  = __fsub_rn(f12, f02);
    g_P[o] = make_float4(mn2, rng, df, f02);
}

// ---------------- kernel 5: elementwise apply (exact op sequence) --------
__device__ __forceinline__ float apply_one(float p, float4 P) {
    float t1  = __fsub_rn(p, P.x);
    float t2  = __fdiv_rn(t1, P.y);
    float t3  = __fmul_rn(t2, P.z);
    float tmp = __fadd_rn(t3, P.w);
    bool bad = bit_isnan(tmp) || bit_iszero(tmp);
    float s = __fdiv_rn(p, bad ? 1.0f : tmp);
    float scale = (bad || bit_nonfinite(s)) ? 0.0f : s;
    return __fmul_rn(p, scale);
}

__global__ __launch_bounds__(256) void k_apply(const float* __restrict__ pr,
                                               const int* __restrict__ vr,
                                               float* __restrict__ out) {
    long base = (long)blockIdx.x * CHUNK;
    int b = blockIdx.x / (Nn / CHUNK);
    const float4* __restrict__ P = g_P + b * Gn;

    int t = threadIdx.x;
    const float4* p4 = (const float4*)(pr + base);
    const int4*   v4 = (const int4*)(vr + base);
    float4*       o4 = (float4*)(out + base);

#pragma unroll 4
    for (int it = 0; it < CHUNK / 1024; ++it) {
        float4 p = p4[it * 256 + t];
        int4   v = v4[it * 256 + t];
        float4 r;
        r.x = apply_one(p.x, __ldg(&P[v.x]));
        r.y = apply_one(p.y, __ldg(&P[v.y]));
        r.z = apply_one(p.z, __ldg(&P[v.z]));
        r.w = apply_one(p.w, __ldg(&P[v.w]));
        o4[it * 256 + t] = r;
    }
}

// ---------------- launch --------------------------------------------------
extern "C" void kernel_launch(void* const* d_in, const int* in_sizes, int n_in,
                              void* d_out, int out_size) {
    const float* pr        = (const float*)d_in[0];
    const float* inp_means = (const float*)d_in[1];
    const int*   vr        = (const int*)d_in[2];
    const float* W         = (const float*)d_in[3];
    float* out = (float*)d_out;

    k_hist<<<NSEG / NWARP, 256>>>(vr);
    k_scan<<<Bn, Gn>>>();
    k_scatter<<<NSEG / NWARP, 256>>>(pr, vr);
    k_params<<<Bn, Gn>>>(inp_means, W);
    k_apply<<<NBLK, 256>>>(pr, vr, out);
}

// round 5
// speedup vs baseline: 1.3672x; 1.3672x over previous
#include <cuda_runtime.h>
#include <math.h>
#include <stdint.h>

#define Bn 32
#define Nn 262144
#define Gn 256
#define SEGSZ 2048              // elements per warp-segment
#define SEGPB (Nn / SEGSZ)      // 128 segments per batch
#define NSEG (Bn * SEGPB)       // 4096 segments
#define NWARP 8                 // warps per block (hist/scatter)
#define CHUNK 16384
#define NBLK ((Bn * Nn) / CHUNK)   // 512

// ---------------- scratch (device globals; no allocation) ----------------
__device__ unsigned g_cnt[NSEG][Gn];   // per-segment counts -> within-batch exclusive prefix
__device__ unsigned g_base[Bn][Gn];    // group base offset within batch
__device__ unsigned g_tot[Bn][Gn];     // group totals
__device__ float    g_sorted[Bn * Nn]; // stable-partitioned pr (n-order within group)
__device__ float4   g_SMM[Bn * Gn];    // per-group (sum, min, max, -)
__device__ float4   g_P[Bn * Gn];      // per-group (mn', rng, df, f0')

__device__ __forceinline__ bool bit_isnan(float f) {
    return (__float_as_uint(f) << 1) > 0xFF000000u;
}
__device__ __forceinline__ bool bit_iszero(float f) {
    return (__float_as_uint(f) << 1) == 0u;
}
__device__ __forceinline__ bool bit_nonfinite(float f) {
    return (__float_as_uint(f) << 1) >= 0xFF000000u;
}

// ---------------- kernel 1: per-segment histogram (warp-private) ---------
__global__ __launch_bounds__(256) void k_hist(const int* __restrict__ vr) {
    __shared__ unsigned s_h[NWARP][Gn];
    int t = threadIdx.x, w = t >> 5, l = t & 31;
    unsigned lt = (1u << l) - 1u;

#pragma unroll
    for (int i = l; i < Gn; i += 32) s_h[w][i] = 0u;
    __syncwarp();

    long seg = (long)blockIdx.x * NWARP + w;
    const int* __restrict__ src = vr + seg * SEGSZ;

#pragma unroll 4
    for (int r = 0; r < SEGSZ / 32; ++r) {
        int g = src[r * 32 + l];
        unsigned m = __match_any_sync(0xFFFFFFFFu, g);
        if ((m & lt) == 0u) s_h[w][g] += __popc(m);   // unique leader per group/round
    }
    __syncwarp();

#pragma unroll
    for (int i = l; i < Gn; i += 32) g_cnt[seg][i] = s_h[w][i];
}

// ---------------- kernel 2: scans (per-batch) ----------------------------
__global__ __launch_bounds__(Gn) void k_scan() {
    int b = blockIdx.x;
    int g = threadIdx.x;

    unsigned run = 0;
#pragma unroll 4
    for (int s = 0; s < SEGPB; ++s) {
        int idx = b * SEGPB + s;
        unsigned c = g_cnt[idx][g];
        g_cnt[idx][g] = run;          // exclusive prefix within batch, per group
        run += c;
    }
    g_tot[b][g] = run;

    __shared__ unsigned sh[Gn];
    sh[g] = run;
    __syncthreads();
    for (int d = 1; d < Gn; d <<= 1) {
        unsigned x = (g >= d) ? sh[g - d] : 0u;
        __syncthreads();
        sh[g] += x;
        __syncthreads();
    }
    g_base[b][g] = sh[g] - run;       // exclusive scan over groups
}

// ---------------- kernel 3: stable scatter (warp-segment, barrier-free) --
__global__ __launch_bounds__(256) void k_scatter(const float* __restrict__ pr,
                                                 const int* __restrict__ vr) {
    __shared__ unsigned s_run[NWARP][Gn];
    int t = threadIdx.x, w = t >> 5, l = t & 31;
    unsigned lt = (1u << l) - 1u;

    long seg = (long)blockIdx.x * NWARP + w;
    int b = (int)(seg >> 7);          // seg / SEGPB

#pragma unroll
    for (int i = l; i < Gn; i += 32)
        s_run[w][i] = g_base[b][i] + g_cnt[seg][i];
    __syncwarp();

    const int*   __restrict__ vs = vr + seg * SEGSZ;
    const float* __restrict__ ps = pr + seg * SEGSZ;
    float* __restrict__ dst = g_sorted + (long)b * Nn;

#pragma unroll 4
    for (int r = 0; r < SEGSZ / 32; ++r) {
        int   g = vs[r * 32 + l];
        float p = ps[r * 32 + l];
        unsigned m = __match_any_sync(0xFFFFFFFFu, g);
        unsigned lr = __popc(m & lt);
        unsigned cur = s_run[w][g];          // all lanes read (program-ordered vs write)
        dst[cur + lr] = p;
        if (lr == 0u) s_run[w][g] = cur + __popc(m);
    }
}

// ---------------- kernel 4: sequential fold (spread + wide loads) --------
__global__ __launch_bounds__(32) void k_fold() {
    int gid = blockIdx.x * 32 + threadIdx.x;   // 0..8191
    int b = gid >> 8, g = gid & 255;

    unsigned cnt  = g_tot[b][g];
    const float* __restrict__ src = g_sorted + (long)b * Nn + g_base[b][g];

    float acc = 0.0f;
    float mn =  __int_as_float(0x7F800000);    // +inf
    float mx = -__int_as_float(0x7F800000);    // -inf

    unsigned i = 0;
    // scalar head until 16B aligned (order-preserving)
    while (i < cnt && ((((uintptr_t)(src + i)) & 15u) != 0u)) {
        float a = src[i];
        acc = __fadd_rn(acc, a);
        mn = fminf(mn, a); mx = fmaxf(mx, a);
        ++i;
    }
    // wide body: 8 independent LDG.128 in flight, then fold in order
    for (; i + 32 <= cnt; i += 32) {
        float4 q[8];
#pragma unroll
        for (int j = 0; j < 8; ++j) q[j] = *(const float4*)(src + i + j * 4);
#pragma unroll
        for (int j = 0; j < 8; ++j) {
            acc = __fadd_rn(acc, q[j].x);
            acc = __fadd_rn(acc, q[j].y);
            acc = __fadd_rn(acc, q[j].z);
            acc = __fadd_rn(acc, q[j].w);
            mn = fminf(mn, fminf(fminf(q[j].x, q[j].y), fminf(q[j].z, q[j].w)));
            mx = fmaxf(mx, fmaxf(fmaxf(q[j].x, q[j].y), fmaxf(q[j].z, q[j].w)));
        }
    }
    for (; i + 4 <= cnt; i += 4) {
        float4 q = *(const float4*)(src + i);
        acc = __fadd_rn(acc, q.x);
        acc = __fadd_rn(acc, q.y);
        acc = __fadd_rn(acc, q.z);
        acc = __fadd_rn(acc, q.w);
        mn = fminf(mn, fminf(fminf(q.x, q.y), fminf(q.z, q.w)));
        mx = fmaxf(mx, fmaxf(fmaxf(q.x, q.y), fmaxf(q.z, q.w)));
    }
    for (; i < cnt; ++i) {
        float a = src[i];
        acc = __fadd_rn(acc, a);
        mn = fminf(mn, a); mx = fmaxf(mx, a);
    }

    g_SMM[gid] = make_float4(acc, mn, mx, 0.0f);
}

// ---------------- kernel 5: sort + per-group affine params ---------------
__global__ __launch_bounds__(Gn) void k_params(const float* __restrict__ inp_means,
                                               const float* __restrict__ W) {
    __shared__ float skey[Gn];
    __shared__ int   sid[Gn];
    __shared__ float f0u[Gn];
    __shared__ float f1u[Gn];

    int b = blockIdx.x;
    int g = threadIdx.x;
    int o = b * Gn + g;

    float4 smm = g_SMM[o];
    unsigned cnt = g_tot[b][g];
    bool any = (cnt > 0u);
    float vsum = any ? smm.x : 0.0f;
    float mn = smm.y, mx = smm.z;

    float W0 = W[0], W1 = W[1];
    float vmean = __fdiv_rn(__fadd_rn(__fmul_rn(inp_means[o], W0),
                                      __fmul_rn(vsum, W1)),
                            __fadd_rn(W0, W1));

    skey[g] = vmean;
    sid[g]  = g;
    __syncthreads();

    // bitonic sort on (value, id) == jax stable argsort
    for (int k = 2; k <= Gn; k <<= 1) {
        for (int j = k >> 1; j > 0; j >>= 1) {
            int ixj = g ^ j;
            if (ixj > g) {
                float a = skey[g], c = skey[ixj];
                int ia = sid[g], ic = sid[ixj];
                bool up = ((g & k) == 0);
                bool gt = (a > c) || (a == c && ia > ic);
                if (gt == up) {
                    skey[g] = c; skey[ixj] = a;
                    sid[g] = ic; sid[ixj] = ia;
                }
            }
            __syncthreads();
        }
    }

    float vsr   = skey[g];
    float vprev = (g == 0)      ? vsr : skey[g - 1];
    float vnext = (g == Gn - 1) ? __fmul_rn(vsr, 2.0f) : skey[g + 1];
    float f0 = __fdiv_rn(__fadd_rn(vprev, vsr), 1.999f);
    float f1 = __fdiv_rn(__fadd_rn(vsr, vnext), 2.001f);
    f0u[sid[g]] = f0;
    f1u[sid[g]] = f1;
    __syncthreads();

    bool ns = (mn == mx);   // empty group: inf == -inf -> false (matches ref)

    float mn2, mx2, f02, f12;
    if (!any) { mn2 = 0.0f; mx2 = 1.0f; f02 = 0.0f; f12 = 0.0f; }
    else {
        mn2 = ns ? 0.0f : mn;
        mx2 = ns ? 1.0f : mx;
        f02 = ns ? 0.0f : f0u[g];
        f12 = ns ? 1.0f : f1u[g];
    }
    float rng = __fsub_rn(mx2, mn2);
    float df  = __fsub_rn(f12, f02);
    g_P[o] = make_float4(mn2, rng, df, f02);
}

// ---------------- kernel 6: elementwise apply (exact op sequence) --------
__device__ __forceinline__ float apply_one(float p, float4 P) {
    float t1  = __fsub_rn(p, P.x);
    float t2  = __fdiv_rn(t1, P.y);
    float t3  = __fmul_rn(t2, P.z);
    float tmp = __fadd_rn(t3, P.w);
    bool bad = bit_isnan(tmp) || bit_iszero(tmp);
    float s = __fdiv_rn(p, bad ? 1.0f : tmp);
    float scale = (bad || bit_nonfinite(s)) ? 0.0f : s;
    return __fmul_rn(p, scale);
}

__global__ __launch_bounds__(256) void k_apply(const float* __restrict__ pr,
                                               const int* __restrict__ vr,
                                               float* __restrict__ out) {
    long base = (long)blockIdx.x * CHUNK;
    int b = blockIdx.x / (Nn / CHUNK);
    const float4* __restrict__ P = g_P + b * Gn;

    int t = threadIdx.x;
    const float4* p4 = (const float4*)(pr + base);
    const int4*   v4 = (const int4*)(vr + base);
    float4*       o4 = (float4*)(out + base);

#pragma unroll 4
    for (int it = 0; it < CHUNK / 1024; ++it) {
        float4 p = p4[it * 256 + t];
        int4   v = v4[it * 256 + t];
        float4 r;
        r.x = apply_one(p.x, __ldg(&P[v.x]));
        r.y = apply_one(p.y, __ldg(&P[v.y]));
        r.z = apply_one(p.z, __ldg(&P[v.z]));
        r.w = apply_one(p.w, __ldg(&P[v.w]));
        o4[it * 256 + t] = r;
    }
}

// ---------------- launch --------------------------------------------------
extern "C" void kernel_launch(void* const* d_in, const int* in_sizes, int n_in,
                              void* d_out, int out_size) {
    const float* pr        = (const float*)d_in[0];
    const float* inp_means = (const float*)d_in[1];
    const int*   vr        = (const int*)d_in[2];
    const float* W         = (const float*)d_in[3];
    float* out = (float*)d_out;

    k_hist<<<NSEG / NWARP, 256>>>(vr);
    k_scan<<<Bn, Gn>>>();
    k_scatter<<<NSEG / NWARP, 256>>>(pr, vr);
    k_fold<<<(Bn * Gn) / 32, 32>>>();
    k_params<<<Bn, Gn>>>(inp_means, W);
    k_apply<<<NBLK, 256>>>(pr, vr, out);
}

// round 6
// speedup vs baseline: 1.4601x; 1.0679x over previous
#include <cuda_runtime.h>
#include <math.h>
#include <stdint.h>

#define Bn 32
#define Nn 262144
#define Gn 256
#define SEGSZ 2048              // elements per warp-segment
#define SEGPB (Nn / SEGSZ)      // 128 segments per batch
#define NSEG (Bn * SEGPB)       // 4096 segments
#define NWARP 8                 // warps per block (hist/scatter)
#define CHUNK 16384
#define NBLK ((Bn * Nn) / CHUNK)   // 512

// ---------------- scratch (device globals; no allocation) ----------------
__device__ unsigned g_cnt[NSEG][Gn];   // counts -> within-batch exclusive prefix (after k_scan)
__device__ unsigned g_base[Bn][Gn];    // group base offset within batch
__device__ unsigned g_tot[Bn][Gn];     // group totals
__device__ float    g_sorted[Bn * Nn]; // stable-partitioned pr (n-order within group)
__device__ float4   g_SMM[Bn * Gn];    // per-group (sum, min, max, -)
__device__ float4   g_P[Bn * Gn];      // per-group (mn', rng, df, f0')

__device__ __forceinline__ bool bit_isnan(float f) {
    return (__float_as_uint(f) << 1) > 0xFF000000u;
}
__device__ __forceinline__ bool bit_iszero(float f) {
    return (__float_as_uint(f) << 1) == 0u;
}
__device__ __forceinline__ bool bit_nonfinite(float f) {
    return (__float_as_uint(f) << 1) >= 0xFF000000u;
}

// ---------------- kernel 1: per-segment histogram (warp-private) ---------
__global__ __launch_bounds__(256) void k_hist(const int* __restrict__ vr) {
    __shared__ unsigned s_h[NWARP][Gn];
    int t = threadIdx.x, w = t >> 5, l = t & 31;
    unsigned lt = (1u << l) - 1u;

#pragma unroll
    for (int i = l; i < Gn; i += 32) s_h[w][i] = 0u;
    __syncwarp();

    long seg = (long)blockIdx.x * NWARP + w;
    const int* __restrict__ src = vr + seg * SEGSZ;

#pragma unroll 4
    for (int r = 0; r < SEGSZ / 32; ++r) {
        int g = src[r * 32 + l];
        unsigned m = __match_any_sync(0xFFFFFFFFu, g);
        if ((m & lt) == 0u) s_h[w][g] += __popc(m);   // unique leader per group/round
    }
    __syncwarp();

#pragma unroll
    for (int i = l; i < Gn; i += 32) g_cnt[seg][i] = s_h[w][i];
}

// ---------------- kernel 2: scans (per-batch) ----------------------------
__global__ __launch_bounds__(Gn) void k_scan() {
    int b = blockIdx.x;
    int g = threadIdx.x;

    unsigned run = 0;
#pragma unroll 8
    for (int s = 0; s < SEGPB; ++s) {
        int idx = b * SEGPB + s;
        unsigned c = g_cnt[idx][g];
        g_cnt[idx][g] = run;          // exclusive prefix within batch, per group
        run += c;
    }
    g_tot[b][g] = run;

    __shared__ unsigned sh[Gn];
    sh[g] = run;
    __syncthreads();
    for (int d = 1; d < Gn; d <<= 1) {
        unsigned x = (g >= d) ? sh[g - d] : 0u;
        __syncthreads();
        sh[g] += x;
        __syncthreads();
    }
    g_base[b][g] = sh[g] - run;       // exclusive scan over groups
}

// ---------------- kernel 3: stable scatter via smem reorder --------------
// dynamic smem layout (per block):
//   float    s_val [NWARP][SEGSZ]   64KB
//   uint8    s_gid [NWARP][SEGSZ]   16KB
//   unsigned s_lrun[NWARP][Gn]       8KB
//   unsigned s_K   [NWARP][Gn]       8KB
#define SCAT_SMEM (NWARP * SEGSZ * 4 + NWARP * SEGSZ + NWARP * Gn * 4 + NWARP * Gn * 4)

__global__ __launch_bounds__(256) void k_scatter(const float* __restrict__ pr,
                                                 const int* __restrict__ vr) {
    extern __shared__ unsigned char sm[];
    int t = threadIdx.x, w = t >> 5, l = t & 31;
    unsigned lt = (1u << l) - 1u;

    float*         s_val  = (float*)sm + (long)w * SEGSZ;
    unsigned char* s_gid  = sm + NWARP * SEGSZ * 4 + w * SEGSZ;
    unsigned*      s_lrun = (unsigned*)(sm + NWARP * SEGSZ * 5) + w * Gn;
    unsigned*      s_K    = (unsigned*)(sm + NWARP * SEGSZ * 5 + NWARP * Gn * 4) + w * Gn;

    long seg = (long)blockIdx.x * NWARP + w;
    int b    = (int)(seg >> 7);       // seg / SEGPB
    int sidx = (int)(seg & (SEGPB - 1));
    bool last = (sidx == SEGPB - 1);

    // ---- phase 0: per-group local counts (prefix-row diff) + warp scan ----
    const uint4* preR  = (const uint4*)g_cnt[seg];
    const uint4* nxtR  = last ? (const uint4*)g_tot[b] : (const uint4*)g_cnt[seg + 1];
    const uint4* gbR   = (const uint4*)g_base[b];

    unsigned pre[8], cnt[8], gb[8];
#pragma unroll
    for (int h = 0; h < 2; ++h) {
        uint4 a = preR[l * 2 + h], c = nxtR[l * 2 + h], d = gbR[l * 2 + h];
        pre[h*4+0] = a.x; pre[h*4+1] = a.y; pre[h*4+2] = a.z; pre[h*4+3] = a.w;
        cnt[h*4+0] = c.x - a.x; cnt[h*4+1] = c.y - a.y;
        cnt[h*4+2] = c.z - a.z; cnt[h*4+3] = c.w - a.w;
        gb[h*4+0] = d.x; gb[h*4+1] = d.y; gb[h*4+2] = d.z; gb[h*4+3] = d.w;
    }
    unsigned lsum = 0;
#pragma unroll
    for (int k = 0; k < 8; ++k) lsum += cnt[k];
    // warp exclusive scan of lane sums
    unsigned sc = lsum;
#pragma unroll
    for (int d = 1; d < 32; d <<= 1) {
        unsigned v = __shfl_up_sync(0xFFFFFFFFu, sc, d);
        if (l >= d) sc += v;
    }
    unsigned running = sc - lsum;     // exclusive
#pragma unroll
    for (int k = 0; k < 8; ++k) {
        int g = l * 8 + k;
        s_lrun[g] = running;                       // lbase
        s_K[g]    = gb[k] + pre[k] - running;      // dest = K[g] + slot
        running  += cnt[k];
    }
    __syncwarp();

    // ---- phase A: rank + stage into smem in stable n-order ----
    const int*   __restrict__ vs = vr + seg * SEGSZ;
    const float* __restrict__ ps = pr + seg * SEGSZ;

#pragma unroll 4
    for (int r = 0; r < SEGSZ / 32; ++r) {
        int   g = vs[r * 32 + l];
        float p = ps[r * 32 + l];
        unsigned m = __match_any_sync(0xFFFFFFFFu, g);
        unsigned lr = __popc(m & lt);
        unsigned cur = s_lrun[g];
        __syncwarp();
        unsigned slot = cur + lr;
        s_val[slot] = p;
        s_gid[slot] = (unsigned char)g;
        if (lr == 0u) s_lrun[g] = cur + __popc(m);
    }
    __syncwarp();

    // ---- phase B: linear sweep -> run-coalesced global stores ----
    float* __restrict__ dst = g_sorted + (long)b * Nn;
#pragma unroll 4
    for (int r = 0; r < SEGSZ / 32; ++r) {
        int s = r * 32 + l;
        int g = s_gid[s];
        dst[s_K[g] + s] = s_val[s];
    }
}

// ---------------- kernel 4: sequential fold (spread + wide loads) --------
__global__ __launch_bounds__(32) void k_fold() {
    int gid = blockIdx.x * 32 + threadIdx.x;   // 0..8191
    int b = gid >> 8, g = gid & 255;

    unsigned cnt  = g_tot[b][g];
    const float* __restrict__ src = g_sorted + (long)b * Nn + g_base[b][g];

    float acc = 0.0f;
    float mn =  __int_as_float(0x7F800000);    // +inf
    float mx = -__int_as_float(0x7F800000);    // -inf

    unsigned i = 0;
    // scalar head until 16B aligned (order-preserving)
    while (i < cnt && ((((uintptr_t)(src + i)) & 15u) != 0u)) {
        float a = src[i];
        acc = __fadd_rn(acc, a);
        mn = fminf(mn, a); mx = fmaxf(mx, a);
        ++i;
    }
    // wide body: 12 independent LDG.128 in flight, then fold in order
    for (; i + 48 <= cnt; i += 48) {
        float4 q[12];
#pragma unroll
        for (int j = 0; j < 12; ++j) q[j] = *(const float4*)(src + i + j * 4);
#pragma unroll
        for (int j = 0; j < 12; ++j) {
            acc = __fadd_rn(acc, q[j].x);
            acc = __fadd_rn(acc, q[j].y);
            acc = __fadd_rn(acc, q[j].z);
            acc = __fadd_rn(acc, q[j].w);
            mn = fminf(mn, fminf(fminf(q[j].x, q[j].y), fminf(q[j].z, q[j].w)));
            mx = fmaxf(mx, fmaxf(fmaxf(q[j].x, q[j].y), fmaxf(q[j].z, q[j].w)));
        }
    }
    for (; i + 4 <= cnt; i += 4) {
        float4 q = *(const float4*)(src + i);
        acc = __fadd_rn(acc, q.x);
        acc = __fadd_rn(acc, q.y);
        acc = __fadd_rn(acc, q.z);
        acc = __fadd_rn(acc, q.w);
        mn = fminf(mn, fminf(fminf(q.x, q.y), fminf(q.z, q.w)));
        mx = fmaxf(mx, fmaxf(fmaxf(q.x, q.y), fmaxf(q.z, q.w)));
    }
    for (; i < cnt; ++i) {
        float a = src[i];
        acc = __fadd_rn(acc, a);
        mn = fminf(mn, a); mx = fmaxf(mx, a);
    }

    g_SMM[gid] = make_float4(acc, mn, mx, 0.0f);
}

// ---------------- kernel 5: sort + per-group affine params ---------------
__global__ __launch_bounds__(Gn) void k_params(const float* __restrict__ inp_means,
                                               const float* __restrict__ W) {
    __shared__ float skey[Gn];
    __shared__ int   sid[Gn];
    __shared__ float f0u[Gn];
    __shared__ float f1u[Gn];

    int b = blockIdx.x;
    int g = threadIdx.x;
    int o = b * Gn + g;

    float4 smm = g_SMM[o];
    unsigned cnt = g_tot[b][g];
    bool any = (cnt > 0u);
    float vsum = any ? smm.x : 0.0f;
    float mn = smm.y, mx = smm.z;

    float W0 = W[0], W1 = W[1];
    float vmean = __fdiv_rn(__fadd_rn(__fmul_rn(inp_means[o], W0),
                                      __fmul_rn(vsum, W1)),
                            __fadd_rn(W0, W1));

    skey[g] = vmean;
    sid[g]  = g;
    __syncthreads();

    // bitonic sort on (value, id) == jax stable argsort
    for (int k = 2; k <= Gn; k <<= 1) {
        for (int j = k >> 1; j > 0; j >>= 1) {
            int ixj = g ^ j;
            if (ixj > g) {
                float a = skey[g], c = skey[ixj];
                int ia = sid[g], ic = sid[ixj];
                bool up = ((g & k) == 0);
                bool gt = (a > c) || (a == c && ia > ic);
                if (gt == up) {
                    skey[g] = c; skey[ixj] = a;
                    sid[g] = ic; sid[ixj] = ia;
                }
            }
            __syncthreads();
        }
    }

    float vsr   = skey[g];
    float vprev = (g == 0)      ? vsr : skey[g - 1];
    float vnext = (g == Gn - 1) ? __fmul_rn(vsr, 2.0f) : skey[g + 1];
    float f0 = __fdiv_rn(__fadd_rn(vprev, vsr), 1.999f);
    float f1 = __fdiv_rn(__fadd_rn(vsr, vnext), 2.001f);
    f0u[sid[g]] = f0;
    f1u[sid[g]] = f1;
    __syncthreads();

    bool ns = (mn == mx);   // empty group: inf == -inf -> false (matches ref)

    float mn2, mx2, f02, f12;
    if (!any) { mn2 = 0.0f; mx2 = 1.0f; f02 = 0.0f; f12 = 0.0f; }
    else {
        mn2 = ns ? 0.0f : mn;
        mx2 = ns ? 1.0f : mx;
        f02 = ns ? 0.0f : f0u[g];
        f12 = ns ? 1.0f : f1u[g];
    }
    float rng = __fsub_rn(mx2, mn2);
    float df  = __fsub_rn(f12, f02);
    g_P[o] = make_float4(mn2, rng, df, f02);
}

// ---------------- kernel 6: elementwise apply (exact op sequence) --------
__device__ __forceinline__ float apply_one(float p, float4 P) {
    float t1  = __fsub_rn(p, P.x);
    float t2  = __fdiv_rn(t1, P.y);
    float t3  = __fmul_rn(t2, P.z);
    float tmp = __fadd_rn(t3, P.w);
    bool bad = bit_isnan(tmp) || bit_iszero(tmp);
    float s = __fdiv_rn(p, bad ? 1.0f : tmp);
    float scale = (bad || bit_nonfinite(s)) ? 0.0f : s;
    return __fmul_rn(p, scale);
}

__global__ __launch_bounds__(256) void k_apply(const float* __restrict__ pr,
                                               const int* __restrict__ vr,
                                               float* __restrict__ out) {
    long base = (long)blockIdx.x * CHUNK;
    int b = blockIdx.x / (Nn / CHUNK);
    const float4* __restrict__ P = g_P + b * Gn;

    int t = threadIdx.x;
    const float4* p4 = (const float4*)(pr + base);
    const int4*   v4 = (const int4*)(vr + base);
    float4*       o4 = (float4*)(out + base);

#pragma unroll 4
    for (int it = 0; it < CHUNK / 1024; ++it) {
        float4 p = p4[it * 256 + t];
        int4   v = v4[it * 256 + t];
        float4 r;
        r.x = apply_one(p.x, __ldg(&P[v.x]));
        r.y = apply_one(p.y, __ldg(&P[v.y]));
        r.z = apply_one(p.z, __ldg(&P[v.z]));
        r.w = apply_one(p.w, __ldg(&P[v.w]));
        o4[it * 256 + t] = r;
    }
}

// ---------------- launch --------------------------------------------------
extern "C" void kernel_launch(void* const* d_in, const int* in_sizes, int n_in,
                              void* d_out, int out_size) {
    const float* pr        = (const float*)d_in[0];
    const float* inp_means = (const float*)d_in[1];
    const int*   vr        = (const int*)d_in[2];
    const float* W         = (const float*)d_in[3];
    float* out = (float*)d_out;

    static int smem_set = 0;
    if (!smem_set) {
        cudaFuncSetAttribute(k_scatter, cudaFuncAttributeMaxDynamicSharedMemorySize,
                             SCAT_SMEM);
        smem_set = 1;
    }

    k_hist<<<NSEG / NWARP, 256>>>(vr);
    k_scan<<<Bn, Gn>>>();
    k_scatter<<<NSEG / NWARP, 256, SCAT_SMEM>>>(pr, vr);
    k_fold<<<(Bn * Gn) / 32, 32>>>();
    k_params<<<Bn, Gn>>>(inp_means, W);
    k_apply<<<NBLK, 256>>>(pr, vr, out);
}

// round 7
// speedup vs baseline: 1.4871x; 1.0185x over previous
#include <cuda_runtime.h>
#include <math.h>
#include <stdint.h>

#define Bn 32
#define Nn 262144
#define Gn 256
#define SEGSZ 2048              // elements per warp-segment
#define SEGPB (Nn / SEGSZ)      // 128 segments per batch
#define NSEG (Bn * SEGPB)       // 4096 segments
#define NWARP 8                 // warps per block (hist/scatter)
#define CHUNK 16384
#define NBLK ((Bn * Nn) / CHUNK)   // 512

// ---------------- scratch (device globals; no allocation) ----------------
__device__ unsigned g_cnt[NSEG][Gn];   // counts -> within-batch exclusive prefix (after k_scan)
__device__ unsigned g_base[Bn][Gn];    // group base offset within batch
__device__ unsigned g_tot[Bn][Gn];     // group totals
__device__ float    g_sorted[Bn * Nn]; // stable-partitioned pr (n-order within group)
__device__ float4   g_SMM[Bn * Gn];    // per-group (sum, min, max, -)
__device__ float4   g_P[Bn * Gn];      // per-group (mn', rng, df, f0')

__device__ __forceinline__ bool bit_isnan(float f) {
    return (__float_as_uint(f) << 1) > 0xFF000000u;
}
__device__ __forceinline__ bool bit_iszero(float f) {
    return (__float_as_uint(f) << 1) == 0u;
}
__device__ __forceinline__ bool bit_nonfinite(float f) {
    return (__float_as_uint(f) << 1) >= 0xFF000000u;
}

// ---------------- kernel 1: per-segment histogram (warp-private) ---------
__global__ __launch_bounds__(256) void k_hist(const int* __restrict__ vr) {
    __shared__ unsigned s_h[NWARP][Gn];
    int t = threadIdx.x, w = t >> 5, l = t & 31;
    unsigned lt = (1u << l) - 1u;

#pragma unroll
    for (int i = l; i < Gn; i += 32) s_h[w][i] = 0u;
    __syncwarp();

    long seg = (long)blockIdx.x * NWARP + w;
    const int4* __restrict__ src = (const int4*)(vr + seg * SEGSZ);

#pragma unroll 2
    for (int r = 0; r < SEGSZ / 128; ++r) {
        int4 v = src[r * 32 + l];
        int gv[4] = {v.x, v.y, v.z, v.w};
#pragma unroll
        for (int e = 0; e < 4; ++e) {
            unsigned m = __match_any_sync(0xFFFFFFFFu, gv[e]);
            if ((m & lt) == 0u) s_h[w][gv[e]] += __popc(m);
        }
    }
    __syncwarp();

#pragma unroll
    for (int i = l; i < Gn; i += 32) g_cnt[seg][i] = s_h[w][i];
}

// ---------------- kernel 2: scans (per-batch) ----------------------------
__global__ __launch_bounds__(Gn) void k_scan() {
    int b = blockIdx.x;
    int g = threadIdx.x;

    unsigned run = 0;
#pragma unroll 8
    for (int s = 0; s < SEGPB; ++s) {
        int idx = b * SEGPB + s;
        unsigned c = g_cnt[idx][g];
        g_cnt[idx][g] = run;          // exclusive prefix within batch, per group
        run += c;
    }
    g_tot[b][g] = run;

    __shared__ unsigned sh[Gn];
    sh[g] = run;
    __syncthreads();
    for (int d = 1; d < Gn; d <<= 1) {
        unsigned x = (g >= d) ? sh[g - d] : 0u;
        __syncthreads();
        sh[g] += x;
        __syncthreads();
    }
    g_base[b][g] = sh[g] - run;       // exclusive scan over groups
}

// ---------------- kernel 3: stable scatter via smem reorder --------------
#define SCAT_SMEM (NWARP * SEGSZ * 4 + NWARP * SEGSZ + NWARP * Gn * 4 + NWARP * Gn * 4)

__global__ __launch_bounds__(256) void k_scatter(const float* __restrict__ pr,
                                                 const int* __restrict__ vr) {
    extern __shared__ unsigned char sm[];
    int t = threadIdx.x, w = t >> 5, l = t & 31;
    unsigned lt = (1u << l) - 1u;

    float*         s_val  = (float*)sm + (long)w * SEGSZ;
    unsigned char* s_gid  = sm + NWARP * SEGSZ * 4 + w * SEGSZ;
    unsigned*      s_lrun = (unsigned*)(sm + NWARP * SEGSZ * 5) + w * Gn;
    unsigned*      s_K    = (unsigned*)(sm + NWARP * SEGSZ * 5 + NWARP * Gn * 4) + w * Gn;

    long seg = (long)blockIdx.x * NWARP + w;
    int b    = (int)(seg >> 7);       // seg / SEGPB
    int sidx = (int)(seg & (SEGPB - 1));
    bool last = (sidx == SEGPB - 1);

    // ---- phase 0: per-group local counts (prefix-row diff) + warp scan ----
    const uint4* preR  = (const uint4*)g_cnt[seg];
    const uint4* nxtR  = last ? (const uint4*)g_tot[b] : (const uint4*)g_cnt[seg + 1];
    const uint4* gbR   = (const uint4*)g_base[b];

    unsigned pre[8], cnt[8], gb[8];
#pragma unroll
    for (int h = 0; h < 2; ++h) {
        uint4 a = preR[l * 2 + h], c = nxtR[l * 2 + h], d = gbR[l * 2 + h];
        pre[h*4+0] = a.x; pre[h*4+1] = a.y; pre[h*4+2] = a.z; pre[h*4+3] = a.w;
        cnt[h*4+0] = c.x - a.x; cnt[h*4+1] = c.y - a.y;
        cnt[h*4+2] = c.z - a.z; cnt[h*4+3] = c.w - a.w;
        gb[h*4+0] = d.x; gb[h*4+1] = d.y; gb[h*4+2] = d.z; gb[h*4+3] = d.w;
    }
    unsigned lsum = 0;
#pragma unroll
    for (int k = 0; k < 8; ++k) lsum += cnt[k];
    unsigned sc = lsum;
#pragma unroll
    for (int d = 1; d < 32; d <<= 1) {
        unsigned v = __shfl_up_sync(0xFFFFFFFFu, sc, d);
        if (l >= d) sc += v;
    }
    unsigned running = sc - lsum;     // exclusive
#pragma unroll
    for (int k = 0; k < 8; ++k) {
        int g = l * 8 + k;
        s_lrun[g] = running;                       // lbase
        s_K[g]    = gb[k] + pre[k] - running;      // dest = K[g] + slot
        running  += cnt[k];
    }
    __syncwarp();

    // ---- phase A: rank + stage into smem in stable n-order ----
    const int*   __restrict__ vs = vr + seg * SEGSZ;
    const float* __restrict__ ps = pr + seg * SEGSZ;

#pragma unroll 4
    for (int r = 0; r < SEGSZ / 32; ++r) {
        int   g = vs[r * 32 + l];
        float p = ps[r * 32 + l];
        unsigned m = __match_any_sync(0xFFFFFFFFu, g);
        unsigned lr = __popc(m & lt);
        unsigned cur = s_lrun[g];
        __syncwarp();
        unsigned slot = cur + lr;
        s_val[slot] = p;
        s_gid[slot] = (unsigned char)g;
        if (lr == 0u) s_lrun[g] = cur + __popc(m);
    }
    __syncwarp();

    // ---- phase B: linear sweep -> run-coalesced global stores ----
    float* __restrict__ dst = g_sorted + (long)b * Nn;
#pragma unroll 4
    for (int r = 0; r < SEGSZ / 32; ++r) {
        int s = r * 32 + l;
        int g = s_gid[s];
        dst[s_K[g] + s] = s_val[s];
    }
}

// ---------------- kernel 4: sequential fold (software-pipelined) ---------
__device__ __forceinline__ void fold8(float4* q, float& acc, float& mn, float& mx) {
#pragma unroll
    for (int j = 0; j < 8; ++j) {
        acc = __fadd_rn(acc, q[j].x);
        acc = __fadd_rn(acc, q[j].y);
        acc = __fadd_rn(acc, q[j].z);
        acc = __fadd_rn(acc, q[j].w);
        mn = fminf(mn, fminf(fminf(q[j].x, q[j].y), fminf(q[j].z, q[j].w)));
        mx = fmaxf(mx, fmaxf(fmaxf(q[j].x, q[j].y), fmaxf(q[j].z, q[j].w)));
    }
}

__global__ __launch_bounds__(32) void k_fold() {
    int gid = blockIdx.x * 32 + threadIdx.x;   // 0..8191
    int b = gid >> 8, g = gid & 255;

    unsigned cnt  = g_tot[b][g];
    const float* __restrict__ src = g_sorted + (long)b * Nn + g_base[b][g];

    float acc = 0.0f;
    float mn =  __int_as_float(0x7F800000);    // +inf
    float mx = -__int_as_float(0x7F800000);    // -inf

    unsigned i = 0;
    // scalar head until 16B aligned (order-preserving)
    while (i < cnt && ((((uintptr_t)(src + i)) & 15u) != 0u)) {
        float a = src[i];
        acc = __fadd_rn(acc, a);
        mn = fminf(mn, a); mx = fmaxf(mx, a);
        ++i;
    }
    // software-pipelined body: next batch's loads issue before current fold
    float4 A[8];
    if (i + 32 <= cnt) {
#pragma unroll
        for (int j = 0; j < 8; ++j) A[j] = *(const float4*)(src + i + j * 4);
    }
    for (; i + 64 <= cnt; i += 32) {
        float4 Bq[8];
#pragma unroll
        for (int j = 0; j < 8; ++j) Bq[j] = *(const float4*)(src + i + 32 + j * 4);
        fold8(A, acc, mn, mx);
#pragma unroll
        for (int j = 0; j < 8; ++j) A[j] = Bq[j];
    }
    if (i + 32 <= cnt) {
        fold8(A, acc, mn, mx);
        i += 32;
    }
    for (; i + 4 <= cnt; i += 4) {
        float4 q = *(const float4*)(src + i);
        acc = __fadd_rn(acc, q.x);
        acc = __fadd_rn(acc, q.y);
        acc = __fadd_rn(acc, q.z);
        acc = __fadd_rn(acc, q.w);
        mn = fminf(mn, fminf(fminf(q.x, q.y), fminf(q.z, q.w)));
        mx = fmaxf(mx, fmaxf(fmaxf(q.x, q.y), fmaxf(q.z, q.w)));
    }
    for (; i < cnt; ++i) {
        float a = src[i];
        acc = __fadd_rn(acc, a);
        mn = fminf(mn, a); mx = fmaxf(mx, a);
    }

    g_SMM[gid] = make_float4(acc, mn, mx, 0.0f);
}

// ---------------- kernel 5: sort + per-group affine params ---------------
__global__ __launch_bounds__(Gn) void k_params(const float* __restrict__ inp_means,
                                               const float* __restrict__ W) {
    __shared__ float skey[Gn];
    __shared__ int   sid[Gn];
    __shared__ float f0u[Gn];
    __shared__ float f1u[Gn];

    int b = blockIdx.x;
    int g = threadIdx.x;
    int o = b * Gn + g;

    float4 smm = g_SMM[o];
    unsigned cnt = g_tot[b][g];
    bool any = (cnt > 0u);
    float vsum = any ? smm.x : 0.0f;
    float mn = smm.y, mx = smm.z;

    float W0 = W[0], W1 = W[1];
    float vmean = __fdiv_rn(__fadd_rn(__fmul_rn(inp_means[o], W0),
                                      __fmul_rn(vsum, W1)),
                            __fadd_rn(W0, W1));

    skey[g] = vmean;
    sid[g]  = g;
    __syncthreads();

    // bitonic sort on (value, id) == jax stable argsort
    for (int k = 2; k <= Gn; k <<= 1) {
        for (int j = k >> 1; j > 0; j >>= 1) {
            int ixj = g ^ j;
            if (ixj > g) {
                float a = skey[g], c = skey[ixj];
                int ia = sid[g], ic = sid[ixj];
                bool up = ((g & k) == 0);
                bool gt = (a > c) || (a == c && ia > ic);
                if (gt == up) {
                    skey[g] = c; skey[ixj] = a;
                    sid[g] = ic; sid[ixj] = ia;
                }
            }
            __syncthreads();
        }
    }

    float vsr   = skey[g];
    float vprev = (g == 0)      ? vsr : skey[g - 1];
    float vnext = (g == Gn - 1) ? __fmul_rn(vsr, 2.0f) : skey[g + 1];
    float f0 = __fdiv_rn(__fadd_rn(vprev, vsr), 1.999f);
    float f1 = __fdiv_rn(__fadd_rn(vsr, vnext), 2.001f);
    f0u[sid[g]] = f0;
    f1u[sid[g]] = f1;
    __syncthreads();

    bool ns = (mn == mx);   // empty group: inf == -inf -> false (matches ref)

    float mn2, mx2, f02, f12;
    if (!any) { mn2 = 0.0f; mx2 = 1.0f; f02 = 0.0f; f12 = 0.0f; }
    else {
        mn2 = ns ? 0.0f : mn;
        mx2 = ns ? 1.0f : mx;
        f02 = ns ? 0.0f : f0u[g];
        f12 = ns ? 1.0f : f1u[g];
    }
    float rng = __fsub_rn(mx2, mn2);
    float df  = __fsub_rn(f12, f02);
    g_P[o] = make_float4(mn2, rng, df, f02);
}

// ---------------- kernel 6: elementwise apply (smem P-cache) -------------
__device__ __forceinline__ float apply_one(float p, float4 P) {
    float t1  = __fsub_rn(p, P.x);
    float t2  = __fdiv_rn(t1, P.y);
    float t3  = __fmul_rn(t2, P.z);
    float tmp = __fadd_rn(t3, P.w);
    bool bad = bit_isnan(tmp) || bit_iszero(tmp);
    float s = __fdiv_rn(p, bad ? 1.0f : tmp);
    float scale = (bad || bit_nonfinite(s)) ? 0.0f : s;
    return __fmul_rn(p, scale);
}

__global__ __launch_bounds__(256) void k_apply(const float* __restrict__ pr,
                                               const int* __restrict__ vr,
                                               float* __restrict__ out) {
    __shared__ float4 sP[Gn];
    long base = (long)blockIdx.x * CHUNK;
    int b = blockIdx.x / (Nn / CHUNK);

    int t = threadIdx.x;
    sP[t] = g_P[b * Gn + t];
    __syncthreads();

    const float4* p4 = (const float4*)(pr + base);
    const int4*   v4 = (const int4*)(vr + base);
    float4*       o4 = (float4*)(out + base);

#pragma unroll 4
    for (int it = 0; it < CHUNK / 1024; ++it) {
        float4 p = p4[it * 256 + t];
        int4   v = v4[it * 256 + t];
        float4 r;
        r.x = apply_one(p.x, sP[v.x]);
        r.y = apply_one(p.y, sP[v.y]);
        r.z = apply_one(p.z, sP[v.z]);
        r.w = apply_one(p.w, sP[v.w]);
        o4[it * 256 + t] = r;
    }
}

// ---------------- launch --------------------------------------------------
extern "C" void kernel_launch(void* const* d_in, const int* in_sizes, int n_in,
                              void* d_out, int out_size) {
    const float* pr        = (const float*)d_in[0];
    const float* inp_means = (const float*)d_in[1];
    const int*   vr        = (const int*)d_in[2];
    const float* W         = (const float*)d_in[3];
    float* out = (float*)d_out;

    static int smem_set = 0;
    if (!smem_set) {
        cudaFuncSetAttribute(k_scatter, cudaFuncAttributeMaxDynamicSharedMemorySize,
                             SCAT_SMEM);
        smem_set = 1;
    }

    k_hist<<<NSEG / NWARP, 256>>>(vr);
    k_scan<<<Bn, Gn>>>();
    k_scatter<<<NSEG / NWARP, 256, SCAT_SMEM>>>(pr, vr);
    k_fold<<<(Bn * Gn) / 32, 32>>>();
    k_params<<<Bn, Gn>>>(inp_means, W);
    k_apply<<<NBLK, 256>>>(pr, vr, out);
}

// round 8
// speedup vs baseline: 1.4978x; 1.0072x over previous
#include <cuda_runtime.h>
#include <math.h>
#include <stdint.h>

#define Bn 32
#define Nn 262144
#define Gn 256
#define SEGSZ 2048              // elements per warp-segment
#define SEGPB (Nn / SEGSZ)      // 128 segments per batch
#define NSEG (Bn * SEGPB)       // 4096 segments
#define NWARP 8                 // warps per block (hist/scatter)
#define CHUNK 16384
#define NBLK ((Bn * Nn) / CHUNK)   // 512

// ---------------- scratch (device globals; no allocation) ----------------
__device__ unsigned g_cnt[NSEG][Gn];   // counts -> within-batch exclusive prefix (after k_scan)
__device__ unsigned g_base[Bn][Gn];    // group base offset within batch
__device__ unsigned g_tot[Bn][Gn];     // group totals
__device__ float    g_sorted[Bn * Nn]; // stable-partitioned pr (n-order within group)
__device__ float4   g_SMM[Bn * Gn];    // per-group (sum, min, max, -)
__device__ float4   g_P[Bn * Gn];      // per-group (mn', rng, df, f0')

__device__ __forceinline__ bool bit_isnan(float f) {
    return (__float_as_uint(f) << 1) > 0xFF000000u;
}
__device__ __forceinline__ bool bit_iszero(float f) {
    return (__float_as_uint(f) << 1) == 0u;
}
__device__ __forceinline__ bool bit_nonfinite(float f) {
    return (__float_as_uint(f) << 1) >= 0xFF000000u;
}

// ---------------- kernel 1: per-segment histogram (warp-private) ---------
__global__ __launch_bounds__(256) void k_hist(const int* __restrict__ vr) {
    __shared__ unsigned s_h[NWARP][Gn];
    int t = threadIdx.x, w = t >> 5, l = t & 31;
    unsigned lt = (1u << l) - 1u;

#pragma unroll
    for (int i = l; i < Gn; i += 32) s_h[w][i] = 0u;
    __syncwarp();

    long seg = (long)blockIdx.x * NWARP + w;
    const int4* __restrict__ src = (const int4*)(vr + seg * SEGSZ);

#pragma unroll 2
    for (int r = 0; r < SEGSZ / 128; ++r) {
        int4 v = src[r * 32 + l];
        int gv[4] = {v.x, v.y, v.z, v.w};
#pragma unroll
        for (int e = 0; e < 4; ++e) {
            unsigned m = __match_any_sync(0xFFFFFFFFu, gv[e]);
            if ((m & lt) == 0u) s_h[w][gv[e]] += __popc(m);
        }
    }
    __syncwarp();

#pragma unroll
    for (int i = l; i < Gn; i += 32) g_cnt[seg][i] = s_h[w][i];
}

// ---------------- kernel 2: scans (per-batch) ----------------------------
__global__ __launch_bounds__(Gn) void k_scan() {
    int b = blockIdx.x;
    int g = threadIdx.x;

    unsigned run = 0;
#pragma unroll 8
    for (int s = 0; s < SEGPB; ++s) {
        int idx = b * SEGPB + s;
        unsigned c = g_cnt[idx][g];
        g_cnt[idx][g] = run;          // exclusive prefix within batch, per group
        run += c;
    }
    g_tot[b][g] = run;

    __shared__ unsigned sh[Gn];
    sh[g] = run;
    __syncthreads();
    for (int d = 1; d < Gn; d <<= 1) {
        unsigned x = (g >= d) ? sh[g - d] : 0u;
        __syncthreads();
        sh[g] += x;
        __syncthreads();
    }
    g_base[b][g] = sh[g] - run;       // exclusive scan over groups
}

// ---------------- kernel 3: stable scatter via smem reorder --------------
#define SCAT_SMEM (NWARP * SEGSZ * 4 + NWARP * SEGSZ + NWARP * Gn * 4 + NWARP * Gn * 4)

__global__ __launch_bounds__(256) void k_scatter(const float* __restrict__ pr,
                                                 const int* __restrict__ vr) {
    extern __shared__ unsigned char sm[];
    int t = threadIdx.x, w = t >> 5, l = t & 31;
    unsigned lt = (1u << l) - 1u;

    float*         s_val  = (float*)sm + (long)w * SEGSZ;
    unsigned char* s_gid  = sm + NWARP * SEGSZ * 4 + w * SEGSZ;
    unsigned*      s_lrun = (unsigned*)(sm + NWARP * SEGSZ * 5) + w * Gn;
    unsigned*      s_K    = (unsigned*)(sm + NWARP * SEGSZ * 5 + NWARP * Gn * 4) + w * Gn;

    long seg = (long)blockIdx.x * NWARP + w;
    int b    = (int)(seg >> 7);       // seg / SEGPB
    int sidx = (int)(seg & (SEGPB - 1));
    bool last = (sidx == SEGPB - 1);

    // ---- phase 0: per-group local counts (prefix-row diff) + warp scan ----
    const uint4* preR  = (const uint4*)g_cnt[seg];
    const uint4* nxtR  = last ? (const uint4*)g_tot[b] : (const uint4*)g_cnt[seg + 1];
    const uint4* gbR   = (const uint4*)g_base[b];

    unsigned pre[8], cnt[8], gb[8];
#pragma unroll
    for (int h = 0; h < 2; ++h) {
        uint4 a = preR[l * 2 + h], c = nxtR[l * 2 + h], d = gbR[l * 2 + h];
        pre[h*4+0] = a.x; pre[h*4+1] = a.y; pre[h*4+2] = a.z; pre[h*4+3] = a.w;
        cnt[h*4+0] = c.x - a.x; cnt[h*4+1] = c.y - a.y;
        cnt[h*4+2] = c.z - a.z; cnt[h*4+3] = c.w - a.w;
        gb[h*4+0] = d.x; gb[h*4+1] = d.y; gb[h*4+2] = d.z; gb[h*4+3] = d.w;
    }
    unsigned lsum = 0;
#pragma unroll
    for (int k = 0; k < 8; ++k) lsum += cnt[k];
    unsigned sc = lsum;
#pragma unroll
    for (int d = 1; d < 32; d <<= 1) {
        unsigned v = __shfl_up_sync(0xFFFFFFFFu, sc, d);
        if (l >= d) sc += v;
    }
    unsigned running = sc - lsum;     // exclusive
#pragma unroll
    for (int k = 0; k < 8; ++k) {
        int g = l * 8 + k;
        s_lrun[g] = running;                       // lbase
        s_K[g]    = gb[k] + pre[k] - running;      // dest = K[g] + slot
        running  += cnt[k];
    }
    __syncwarp();

    // ---- phase A: rank + stage into smem in stable n-order ----
    const int*   __restrict__ vs = vr + seg * SEGSZ;
    const float* __restrict__ ps = pr + seg * SEGSZ;

#pragma unroll 4
    for (int r = 0; r < SEGSZ / 32; ++r) {
        int   g = vs[r * 32 + l];
        float p = ps[r * 32 + l];
        unsigned m = __match_any_sync(0xFFFFFFFFu, g);
        unsigned lr = __popc(m & lt);
        unsigned cur = s_lrun[g];
        __syncwarp();
        unsigned slot = cur + lr;
        s_val[slot] = p;
        s_gid[slot] = (unsigned char)g;
        if (lr == 0u) s_lrun[g] = cur + __popc(m);
    }
    __syncwarp();

    // ---- phase B: linear sweep -> run-coalesced global stores ----
    float* __restrict__ dst = g_sorted + (long)b * Nn;
#pragma unroll 4
    for (int r = 0; r < SEGSZ / 32; ++r) {
        int s = r * 32 + l;
        int g = s_gid[s];
        dst[s_K[g] + s] = s_val[s];
    }
}

// ---------------- kernel 4: sequential fold (dist-2 pipeline) ------------
__device__ __forceinline__ void fold8(float4* q, float& acc, float& mn, float& mx) {
#pragma unroll
    for (int j = 0; j < 8; ++j) {
        acc = __fadd_rn(acc, q[j].x);
        acc = __fadd_rn(acc, q[j].y);
        acc = __fadd_rn(acc, q[j].z);
        acc = __fadd_rn(acc, q[j].w);
        mn = fminf(mn, fminf(fminf(q[j].x, q[j].y), fminf(q[j].z, q[j].w)));
        mx = fmaxf(mx, fmaxf(fmaxf(q[j].x, q[j].y), fmaxf(q[j].z, q[j].w)));
    }
}

__global__ __launch_bounds__(32) void k_fold() {
    int gid = blockIdx.x * 32 + threadIdx.x;   // 0..8191
    int b = gid >> 8, g = gid & 255;

    unsigned cnt  = g_tot[b][g];
    const float* __restrict__ src = g_sorted + (long)b * Nn + g_base[b][g];

    float acc = 0.0f;
    float mn =  __int_as_float(0x7F800000);    // +inf
    float mx = -__int_as_float(0x7F800000);    // -inf

    unsigned i = 0;
    // scalar head until 16B aligned (order-preserving)
    while (i < cnt && ((((uintptr_t)(src + i)) & 15u) != 0u)) {
        float a = src[i];
        acc = __fadd_rn(acc, a);
        mn = fminf(mn, a); mx = fmaxf(mx, a);
        ++i;
    }
    // dist-2 software pipeline: two 32-elem batches in flight
    float4 A[8], Bq[8];
    if (i + 32 <= cnt) {
#pragma unroll
        for (int j = 0; j < 8; ++j) A[j] = *(const float4*)(src + i + j * 4);
    }
    if (i + 64 <= cnt) {
#pragma unroll
        for (int j = 0; j < 8; ++j) Bq[j] = *(const float4*)(src + i + 32 + j * 4);
    }
    for (; i + 96 <= cnt; i += 32) {
        float4 C[8];
#pragma unroll
        for (int j = 0; j < 8; ++j) C[j] = *(const float4*)(src + i + 64 + j * 4);
        fold8(A, acc, mn, mx);
#pragma unroll
        for (int j = 0; j < 8; ++j) { A[j] = Bq[j]; Bq[j] = C[j]; }
    }
    if (i + 64 <= cnt) {
        fold8(A, acc, mn, mx);
#pragma unroll
        for (int j = 0; j < 8; ++j) A[j] = Bq[j];
        i += 32;
    }
    if (i + 32 <= cnt) {
        fold8(A, acc, mn, mx);
        i += 32;
    }
    for (; i + 4 <= cnt; i += 4) {
        float4 q = *(const float4*)(src + i);
        acc = __fadd_rn(acc, q.x);
        acc = __fadd_rn(acc, q.y);
        acc = __fadd_rn(acc, q.z);
        acc = __fadd_rn(acc, q.w);
        mn = fminf(mn, fminf(fminf(q.x, q.y), fminf(q.z, q.w)));
        mx = fmaxf(mx, fmaxf(fmaxf(q.x, q.y), fmaxf(q.z, q.w)));
    }
    for (; i < cnt; ++i) {
        float a = src[i];
        acc = __fadd_rn(acc, a);
        mn = fminf(mn, a); mx = fmaxf(mx, a);
    }

    g_SMM[gid] = make_float4(acc, mn, mx, 0.0f);
}

// ---------------- kernel 5: sort + per-group affine params ---------------
__global__ __launch_bounds__(Gn) void k_params(const float* __restrict__ inp_means,
                                               const float* __restrict__ W) {
    __shared__ float skey[Gn];
    __shared__ int   sid[Gn];
    __shared__ float f0u[Gn];
    __shared__ float f1u[Gn];

    int b = blockIdx.x;
    int g = threadIdx.x;
    int o = b * Gn + g;

    float4 smm = g_SMM[o];
    unsigned cnt = g_tot[b][g];
    bool any = (cnt > 0u);
    float vsum = any ? smm.x : 0.0f;
    float mn = smm.y, mx = smm.z;

    float W0 = W[0], W1 = W[1];
    float vmean = __fdiv_rn(__fadd_rn(__fmul_rn(inp_means[o], W0),
                                      __fmul_rn(vsum, W1)),
                            __fadd_rn(W0, W1));

    skey[g] = vmean;
    sid[g]  = g;
    __syncthreads();

    // bitonic sort on (value, id) == jax stable argsort
    for (int k = 2; k <= Gn; k <<= 1) {
        for (int j = k >> 1; j > 0; j >>= 1) {
            int ixj = g ^ j;
            if (ixj > g) {
                float a = skey[g], c = skey[ixj];
                int ia = sid[g], ic = sid[ixj];
                bool up = ((g & k) == 0);
                bool gt = (a > c) || (a == c && ia > ic);
                if (gt == up) {
                    skey[g] = c; skey[ixj] = a;
                    sid[g] = ic; sid[ixj] = ia;
                }
            }
            __syncthreads();
        }
    }

    float vsr   = skey[g];
    float vprev = (g == 0)      ? vsr : skey[g - 1];
    float vnext = (g == Gn - 1) ? __fmul_rn(vsr, 2.0f) : skey[g + 1];
    float f0 = __fdiv_rn(__fadd_rn(vprev, vsr), 1.999f);
    float f1 = __fdiv_rn(__fadd_rn(vsr, vnext), 2.001f);
    f0u[sid[g]] = f0;
    f1u[sid[g]] = f1;
    __syncthreads();

    bool ns = (mn == mx);   // empty group: inf == -inf -> false (matches ref)

    float mn2, mx2, f02, f12;
    if (!any) { mn2 = 0.0f; mx2 = 1.0f; f02 = 0.0f; f12 = 0.0f; }
    else {
        mn2 = ns ? 0.0f : mn;
        mx2 = ns ? 1.0f : mx;
        f02 = ns ? 0.0f : f0u[g];
        f12 = ns ? 1.0f : f1u[g];
    }
    float rng = __fsub_rn(mx2, mn2);
    float df  = __fsub_rn(f12, f02);
    g_P[o] = make_float4(mn2, rng, df, f02);
}

// ---------------- kernel 6: elementwise apply --------------------------
// div #1 (t1/rng) stays exact: its bits set tmp for the error-amplified
// near-zero-tmp elements. div #2 (p/tmp) replaced by MUFU.RCP: error is
// relative-to-s uniformly (~1e-7), no amplification.
__device__ __forceinline__ float apply_one(float p, float4 P) {
    float t1  = __fsub_rn(p, P.x);
    float t2  = __fdiv_rn(t1, P.y);
    float t3  = __fmul_rn(t2, P.z);
    float tmp = __fadd_rn(t3, P.w);
    bool bad = bit_isnan(tmp) || bit_iszero(tmp);
    float den = bad ? 1.0f : tmp;
    float r;
    asm("rcp.approx.f32 %0, %1;" : "=f"(r) : "f"(den));
    float s = __fmul_rn(p, r);
    float scale = (bad || bit_nonfinite(s)) ? 0.0f : s;
    return __fmul_rn(p, scale);
}

__global__ __launch_bounds__(256) void k_apply(const float* __restrict__ pr,
                                               const int* __restrict__ vr,
                                               float* __restrict__ out) {
    __shared__ float4 sP[Gn];
    long base = (long)blockIdx.x * CHUNK;
    int b = blockIdx.x / (Nn / CHUNK);

    int t = threadIdx.x;
    sP[t] = g_P[b * Gn + t];
    __syncthreads();

    const float4* p4 = (const float4*)(pr + base);
    const int4*   v4 = (const int4*)(vr + base);
    float4*       o4 = (float4*)(out + base);

#pragma unroll 4
    for (int it = 0; it < CHUNK / 1024; ++it) {
        float4 p = p4[it * 256 + t];
        int4   v = v4[it * 256 + t];
        float4 r;
        r.x = apply_one(p.x, sP[v.x]);
        r.y = apply_one(p.y, sP[v.y]);
        r.z = apply_one(p.z, sP[v.z]);
        r.w = apply_one(p.w, sP[v.w]);
        o4[it * 256 + t] = r;
    }
}

// ---------------- launch --------------------------------------------------
extern "C" void kernel_launch(void* const* d_in, const int* in_sizes, int n_in,
                              void* d_out, int out_size) {
    const float* pr        = (const float*)d_in[0];
    const float* inp_means = (const float*)d_in[1];
    const int*   vr        = (const int*)d_in[2];
    const float* W         = (const float*)d_in[3];
    float* out = (float*)d_out;

    static int smem_set = 0;
    if (!smem_set) {
        cudaFuncSetAttribute(k_scatter, cudaFuncAttributeMaxDynamicSharedMemorySize,
                             SCAT_SMEM);
        smem_set = 1;
    }

    k_hist<<<NSEG / NWARP, 256>>>(vr);
    k_scan<<<Bn, Gn>>>();
    k_scatter<<<NSEG / NWARP, 256, SCAT_SMEM>>>(pr, vr);
    k_fold<<<(Bn * Gn) / 32, 32>>>();
    k_params<<<Bn, Gn>>>(inp_means, W);
    k_apply<<<NBLK, 256>>>(pr, vr, out);
}